// round 1
// baseline (speedup 1.0000x reference)
#include <cuda_runtime.h>
#include <math.h>

#define N_TOK 4096
#define CDIM 256
#define NH 8
#define HD 32
#define SCALE_F 0.17677669529663687f   // 32^-0.5

// ---- scratch (device globals: no allocation allowed) ----
__device__ float g_q[NH * N_TOK * HD];
__device__ float g_k[NH * N_TOK * HD];
__device__ float g_v[NH * N_TOK * HD];
__device__ float g_ao[N_TOK * CDIM];      // attention output, [n][h*32+d]
__device__ float g_kmask[N_TOK];          // 0.f if kept, -1e30f otherwise

// ============================================================
// Keep mask: keep = 3x3 dilation of (dbz >= 15). (valid | boundary == dilated)
// ============================================================
__global__ void keep_kernel(const float* __restrict__ dbz) {
    int n = blockIdx.x * 256 + threadIdx.x;
    if (n >= N_TOK) return;
    int t   = n >> 10;        // 32*32 = 1024 per frame
    int rem = n & 1023;
    int y   = rem >> 5;
    int x   = rem & 31;
    const float* d = dbz + t * 1024;
    bool k = false;
    #pragma unroll
    for (int dy = -1; dy <= 1; dy++) {
        int yy = y + dy;
        if (yy < 0 || yy >= 32) continue;
        #pragma unroll
        for (int dx = -1; dx <= 1; dx++) {
            int xx = x + dx;
            if (xx < 0 || xx >= 32) continue;
            k = k || (d[yy * 32 + xx] >= 15.0f);
        }
    }
    g_kmask[n] = k ? 0.0f : -1e30f;
}

// ============================================================
// Tiled SGEMM: C[M,N] = A[M,256] * B[N,256]^T   (both K-major)
// BM=BN=64, BK=16, 256 threads, 4x4 micro-tile.
// MODE 0: QKV projection -> scatter into g_q/g_k/g_v (head-major)
// MODE 1: proj           -> out = (keep ? acc+bias : 0) + x   (A is g_ao)
// ============================================================
#define BM 64
#define BN 64
#define BK 16

template <int MODE>
__global__ __launch_bounds__(256) void gemm_kernel(
    const float* __restrict__ A, const float* __restrict__ B,
    const float* __restrict__ bias, const float* __restrict__ xres,
    float* __restrict__ out)
{
    __shared__ float As[BK][BM];
    __shared__ float Bs[BK][BN];

    const float* Ap = (MODE == 0) ? A : g_ao;

    const int tid  = threadIdx.x;
    const int tx   = tid & 15;
    const int ty   = tid >> 4;
    const int row0 = blockIdx.y * BM;
    const int col0 = blockIdx.x * BN;

    const int lm = tid >> 2;          // 0..63
    const int lk = (tid & 3) << 2;    // 0,4,8,12

    float acc[4][4];
    #pragma unroll
    for (int i = 0; i < 4; i++)
        #pragma unroll
        for (int j = 0; j < 4; j++) acc[i][j] = 0.0f;

    for (int k0 = 0; k0 < CDIM; k0 += BK) {
        float4 av = *(const float4*)&Ap[(row0 + lm) * CDIM + k0 + lk];
        float4 bv = *(const float4*)&B [(col0 + lm) * CDIM + k0 + lk];
        As[lk + 0][lm] = av.x; As[lk + 1][lm] = av.y;
        As[lk + 2][lm] = av.z; As[lk + 3][lm] = av.w;
        Bs[lk + 0][lm] = bv.x; Bs[lk + 1][lm] = bv.y;
        Bs[lk + 2][lm] = bv.z; Bs[lk + 3][lm] = bv.w;
        __syncthreads();
        #pragma unroll
        for (int kk = 0; kk < BK; kk++) {
            float4 a = *(const float4*)&As[kk][ty << 2];
            float4 b = *(const float4*)&Bs[kk][tx << 2];
            acc[0][0] += a.x * b.x; acc[0][1] += a.x * b.y;
            acc[0][2] += a.x * b.z; acc[0][3] += a.x * b.w;
            acc[1][0] += a.y * b.x; acc[1][1] += a.y * b.y;
            acc[1][2] += a.y * b.z; acc[1][3] += a.y * b.w;
            acc[2][0] += a.z * b.x; acc[2][1] += a.z * b.y;
            acc[2][2] += a.z * b.z; acc[2][3] += a.z * b.w;
            acc[3][0] += a.w * b.x; acc[3][1] += a.w * b.y;
            acc[3][2] += a.w * b.z; acc[3][3] += a.w * b.w;
        }
        __syncthreads();
    }

    if (MODE == 0) {
        #pragma unroll
        for (int i = 0; i < 4; i++) {
            int n = row0 + (ty << 2) + i;
            #pragma unroll
            for (int j = 0; j < 4; j++) {
                int jg  = col0 + (tx << 2) + j;
                int part = jg >> 8;            // 0=q,1=k,2=v
                int c    = jg & 255;
                int hh   = c >> 5;
                int dd   = c & 31;
                float* dst = (part == 0) ? g_q : (part == 1) ? g_k : g_v;
                dst[(hh * N_TOK + n) * HD + dd] = acc[i][j];
            }
        }
    } else {
        #pragma unroll
        for (int i = 0; i < 4; i++) {
            int n = row0 + (ty << 2) + i;
            bool keep = (g_kmask[n] == 0.0f);
            #pragma unroll
            for (int j = 0; j < 4; j++) {
                int jg = col0 + (tx << 2) + j;
                float v = keep ? (acc[i][j] + bias[jg]) : 0.0f;
                out[n * CDIM + jg] = v + xres[n * CDIM + jg];
            }
        }
    }
}

// ============================================================
// Flash attention (fp32): grid (64 q-tiles, 8 heads), 64 threads,
// one query per thread. K/V tiles of 64 keys in smem (broadcast reads).
// Two-pass per tile with per-thread score row in smem.
// ============================================================
__global__ __launch_bounds__(64) void flash_kernel() {
    const int head = blockIdx.y;
    const int tid  = threadIdx.x;
    const int qi   = blockIdx.x * 64 + tid;

    const float* Q = g_q + head * N_TOK * HD;
    const float* K = g_k + head * N_TOK * HD;
    const float* V = g_v + head * N_TOK * HD;

    __shared__ float Ks[64 * 32];
    __shared__ float Vs[64 * 32];
    __shared__ float Ss[64][65];     // stride 65: conflict-free per-lane rows
    __shared__ float maskadd[64];

    float q[32];
    #pragma unroll
    for (int c = 0; c < 32; c += 4) {
        float4 t = *(const float4*)&Q[qi * 32 + c];
        q[c + 0] = t.x * SCALE_F; q[c + 1] = t.y * SCALE_F;
        q[c + 2] = t.z * SCALE_F; q[c + 3] = t.w * SCALE_F;
    }

    float m = -1e30f, l = 0.0f;
    float acc[32];
    #pragma unroll
    for (int c = 0; c < 32; c++) acc[c] = 0.0f;

    for (int kt = 0; kt < N_TOK; kt += 64) {
        __syncthreads();
        // 64 rows * 32 floats = 2048 floats, contiguous in global -> 512 float4
        const float4* Kg = (const float4*)&K[kt * 32];
        const float4* Vg = (const float4*)&V[kt * 32];
        float4* Ksh = (float4*)Ks;
        float4* Vsh = (float4*)Vs;
        #pragma unroll
        for (int i = 0; i < 8; i++) {
            int idx = tid + i * 64;
            Ksh[idx] = Kg[idx];
            Vsh[idx] = Vg[idx];
        }
        maskadd[tid] = g_kmask[kt + tid];
        __syncthreads();

        // pass 1: scores
        float tmax = -1e30f;
        #pragma unroll 2
        for (int k = 0; k < 64; k++) {
            const float4* kr = (const float4*)&Ks[k * 32];
            float s = 0.0f;
            #pragma unroll
            for (int c4 = 0; c4 < 8; c4++) {
                float4 kv = kr[c4];
                s = fmaf(q[c4 * 4 + 0], kv.x, s);
                s = fmaf(q[c4 * 4 + 1], kv.y, s);
                s = fmaf(q[c4 * 4 + 2], kv.z, s);
                s = fmaf(q[c4 * 4 + 3], kv.w, s);
            }
            s += maskadd[k];
            Ss[tid][k] = s;
            tmax = fmaxf(tmax, s);
        }

        float mn   = fmaxf(m, tmax);
        float corr = __expf(m - mn);
        l *= corr;
        #pragma unroll
        for (int c = 0; c < 32; c++) acc[c] *= corr;

        // pass 2: exp + AV
        #pragma unroll 2
        for (int k = 0; k < 64; k++) {
            float p = __expf(Ss[tid][k] - mn);
            l += p;
            const float4* vr = (const float4*)&Vs[k * 32];
            #pragma unroll
            for (int c4 = 0; c4 < 8; c4++) {
                float4 vv = vr[c4];
                acc[c4 * 4 + 0] = fmaf(p, vv.x, acc[c4 * 4 + 0]);
                acc[c4 * 4 + 1] = fmaf(p, vv.y, acc[c4 * 4 + 1]);
                acc[c4 * 4 + 2] = fmaf(p, vv.z, acc[c4 * 4 + 2]);
                acc[c4 * 4 + 3] = fmaf(p, vv.w, acc[c4 * 4 + 3]);
            }
        }
        m = mn;
    }

    float inv = (l > 0.0f) ? (1.0f / l) : 0.0f;
    float* dst = &g_ao[qi * CDIM + head * HD];
    #pragma unroll
    for (int c = 0; c < 32; c += 4) {
        float4 o;
        o.x = acc[c + 0] * inv; o.y = acc[c + 1] * inv;
        o.z = acc[c + 2] * inv; o.w = acc[c + 3] * inv;
        *(float4*)&dst[c] = o;
    }
}

// ============================================================
extern "C" void kernel_launch(void* const* d_in, const int* in_sizes, int n_in,
                              void* d_out, int out_size) {
    const float* x      = (const float*)d_in[0];  // (1,4,32,32,256)
    const float* dbz    = (const float*)d_in[1];  // (1,4,32,32,1)
    const float* qkv_w  = (const float*)d_in[2];  // (768,256)
    const float* proj_w = (const float*)d_in[3];  // (256,256)
    const float* proj_b = (const float*)d_in[4];  // (256,)
    float* out = (float*)d_out;

    keep_kernel<<<16, 256>>>(dbz);
    gemm_kernel<0><<<dim3(768 / BN, N_TOK / BM), 256>>>(x, qkv_w, nullptr, nullptr, nullptr);
    flash_kernel<<<dim3(N_TOK / 64, NH), 64>>>();
    gemm_kernel<1><<<dim3(CDIM / BN, N_TOK / BM), 256>>>(nullptr, proj_w, proj_b, x, out);
}

// round 3
// speedup vs baseline: 2.6009x; 2.6009x over previous
#include <cuda_runtime.h>
#include <math.h>
#include <stdint.h>

#define N_TOK 4096
#define CDIM 256
#define NH 8
#define HD 32
#define SCALE_F 0.17677669529663687f   // 32^-0.5

// ---- scratch (device globals: no allocation allowed) ----
__device__ float g_q[NH * N_TOK * HD];
__device__ float g_k[NH * N_TOK * HD];
__device__ float g_v[NH * N_TOK * HD];
__device__ float g_ao[N_TOK * CDIM];      // attention output, [n][h*32+d]
__device__ float g_kmask[N_TOK];          // 0.f if kept, -1e30f otherwise

// ============================================================
// Keep mask: keep = 3x3 dilation of (dbz >= 15)
// ============================================================
__global__ void keep_kernel(const float* __restrict__ dbz) {
    int n = blockIdx.x * 256 + threadIdx.x;
    if (n >= N_TOK) return;
    int t   = n >> 10;
    int rem = n & 1023;
    int y   = rem >> 5;
    int x   = rem & 31;
    const float* d = dbz + t * 1024;
    bool k = false;
    #pragma unroll
    for (int dy = -1; dy <= 1; dy++) {
        int yy = y + dy;
        if (yy < 0 || yy >= 32) continue;
        #pragma unroll
        for (int dx = -1; dx <= 1; dx++) {
            int xx = x + dx;
            if (xx < 0 || xx >= 32) continue;
            k = k || (d[yy * 32 + xx] >= 15.0f);
        }
    }
    g_kmask[n] = k ? 0.0f : -1e30f;
}

// ============================================================
// Tiled SGEMM (unchanged from R1): C[M,N] = A[M,256] * B[N,256]^T
// ============================================================
#define BM 64
#define BN 64
#define BK 16

template <int MODE>
__global__ __launch_bounds__(256) void gemm_kernel(
    const float* __restrict__ A, const float* __restrict__ B,
    const float* __restrict__ bias, const float* __restrict__ xres,
    float* __restrict__ out)
{
    __shared__ float As[BK][BM];
    __shared__ float Bs[BK][BN];

    const float* Ap = (MODE == 0) ? A : g_ao;

    const int tid  = threadIdx.x;
    const int tx   = tid & 15;
    const int ty   = tid >> 4;
    const int row0 = blockIdx.y * BM;
    const int col0 = blockIdx.x * BN;

    const int lm = tid >> 2;
    const int lk = (tid & 3) << 2;

    float acc[4][4];
    #pragma unroll
    for (int i = 0; i < 4; i++)
        #pragma unroll
        for (int j = 0; j < 4; j++) acc[i][j] = 0.0f;

    for (int k0 = 0; k0 < CDIM; k0 += BK) {
        float4 av = *(const float4*)&Ap[(row0 + lm) * CDIM + k0 + lk];
        float4 bv = *(const float4*)&B [(col0 + lm) * CDIM + k0 + lk];
        As[lk + 0][lm] = av.x; As[lk + 1][lm] = av.y;
        As[lk + 2][lm] = av.z; As[lk + 3][lm] = av.w;
        Bs[lk + 0][lm] = bv.x; Bs[lk + 1][lm] = bv.y;
        Bs[lk + 2][lm] = bv.z; Bs[lk + 3][lm] = bv.w;
        __syncthreads();
        #pragma unroll
        for (int kk = 0; kk < BK; kk++) {
            float4 a = *(const float4*)&As[kk][ty << 2];
            float4 b = *(const float4*)&Bs[kk][tx << 2];
            acc[0][0] += a.x * b.x; acc[0][1] += a.x * b.y;
            acc[0][2] += a.x * b.z; acc[0][3] += a.x * b.w;
            acc[1][0] += a.y * b.x; acc[1][1] += a.y * b.y;
            acc[1][2] += a.y * b.z; acc[1][3] += a.y * b.w;
            acc[2][0] += a.z * b.x; acc[2][1] += a.z * b.y;
            acc[2][2] += a.z * b.z; acc[2][3] += a.z * b.w;
            acc[3][0] += a.w * b.x; acc[3][1] += a.w * b.y;
            acc[3][2] += a.w * b.z; acc[3][3] += a.w * b.w;
        }
        __syncthreads();
    }

    if (MODE == 0) {
        #pragma unroll
        for (int i = 0; i < 4; i++) {
            int n = row0 + (ty << 2) + i;
            #pragma unroll
            for (int j = 0; j < 4; j++) {
                int jg  = col0 + (tx << 2) + j;
                int part = jg >> 8;
                int c    = jg & 255;
                int hh   = c >> 5;
                int dd   = c & 31;
                float* dst = (part == 0) ? g_q : (part == 1) ? g_k : g_v;
                dst[(hh * N_TOK + n) * HD + dd] = acc[i][j];
            }
        }
    } else {
        #pragma unroll
        for (int i = 0; i < 4; i++) {
            int n = row0 + (ty << 2) + i;
            bool keep = (g_kmask[n] == 0.0f);
            #pragma unroll
            for (int j = 0; j < 4; j++) {
                int jg = col0 + (tx << 2) + j;
                float v = keep ? (acc[i][j] + bias[jg]) : 0.0f;
                out[n * CDIM + jg] = v + xres[n * CDIM + jg];
            }
        }
    }
}

// ============================================================
// Flash attention v2 on tensor cores (tf32 mma.sync m16n8k8).
// Grid (64 q-tiles, 8 heads), 128 threads = 4 warps.
// Each warp: 16 query rows. K-tiles of 64 keys.
// ============================================================
__device__ __forceinline__ uint32_t f2tf(float f) {
    uint32_t r; asm("cvt.rna.tf32.f32 %0, %1;" : "=r"(r) : "f"(f)); return r;
}

__device__ __forceinline__ void mma_tf32(float c[4], const uint32_t a[4],
                                         uint32_t b0, uint32_t b1) {
    asm volatile(
        "mma.sync.aligned.m16n8k8.row.col.f32.tf32.tf32.f32 "
        "{%0,%1,%2,%3},{%4,%5,%6,%7},{%8,%9},{%0,%1,%2,%3};"
        : "+f"(c[0]), "+f"(c[1]), "+f"(c[2]), "+f"(c[3])
        : "r"(a[0]), "r"(a[1]), "r"(a[2]), "r"(a[3]), "r"(b0), "r"(b1));
}

__global__ __launch_bounds__(128) void flash_tc_kernel() {
    const int head = blockIdx.y;
    const int qt   = blockIdx.x * 64;
    const int warp = threadIdx.x >> 5;
    const int lane = threadIdx.x & 31;
    const int grp  = lane >> 2;       // 0..7
    const int tig  = lane & 3;        // 0..3

    const float* Q = g_q + head * N_TOK * HD;
    const float* K = g_k + head * N_TOK * HD;
    const float* V = g_v + head * N_TOK * HD;

    __shared__ uint32_t Ks[64][36];   // K tile as tf32, stride 36 (conflict-free)
    __shared__ uint32_t Vt[32][68];   // V tile transposed [d][key], stride 68
    __shared__ uint32_t Ps[64][68];   // P as tf32, per-warp private 16-row bands
    __shared__ float maskadd[64];

    // --- load Q A-fragments (one-time, direct from gmem, pre-scaled) ---
    const int qr0 = qt + warp * 16 + grp;
    const int qr1 = qr0 + 8;
    uint32_t qa[4][4];
    #pragma unroll
    for (int kc = 0; kc < 4; kc++) {
        int c0 = kc * 8 + tig;
        qa[kc][0] = f2tf(Q[qr0 * HD + c0]     * SCALE_F);
        qa[kc][1] = f2tf(Q[qr1 * HD + c0]     * SCALE_F);
        qa[kc][2] = f2tf(Q[qr0 * HD + c0 + 4] * SCALE_F);
        qa[kc][3] = f2tf(Q[qr1 * HD + c0 + 4] * SCALE_F);
    }

    float m0 = -1e30f, m1 = -1e30f, l0 = 0.0f, l1 = 0.0f;
    float o[4][4];
    #pragma unroll
    for (int nb = 0; nb < 4; nb++)
        #pragma unroll
        for (int j = 0; j < 4; j++) o[nb][j] = 0.0f;

    for (int kt = 0; kt < N_TOK; kt += 64) {
        __syncthreads();
        // --- stage K (as tf32, [key][dim] stride 36) and V^T ([dim][key] stride 68) ---
        #pragma unroll
        for (int i = 0; i < 4; i++) {
            int idx = threadIdx.x + i * 128;     // 0..511
            int row = idx >> 3;
            int c4  = (idx & 7) << 2;
            float4 kv = *(const float4*)&K[(kt + row) * HD + c4];
            Ks[row][c4 + 0] = f2tf(kv.x); Ks[row][c4 + 1] = f2tf(kv.y);
            Ks[row][c4 + 2] = f2tf(kv.z); Ks[row][c4 + 3] = f2tf(kv.w);
            float4 vv = *(const float4*)&V[(kt + row) * HD + c4];
            Vt[c4 + 0][row] = f2tf(vv.x); Vt[c4 + 1][row] = f2tf(vv.y);
            Vt[c4 + 2][row] = f2tf(vv.z); Vt[c4 + 3][row] = f2tf(vv.w);
        }
        if (threadIdx.x < 64) maskadd[threadIdx.x] = g_kmask[kt + threadIdx.x];
        __syncthreads();

        // --- S = Q K^T  (8 n-blocks of 8 keys) ---
        float sc[8][4];
        #pragma unroll
        for (int nb = 0; nb < 8; nb++) {
            sc[nb][0] = sc[nb][1] = sc[nb][2] = sc[nb][3] = 0.0f;
            #pragma unroll
            for (int kc = 0; kc < 4; kc++) {
                uint32_t b0 = Ks[nb * 8 + grp][kc * 8 + tig];
                uint32_t b1 = Ks[nb * 8 + grp][kc * 8 + tig + 4];
                mma_tf32(sc[nb], qa[kc], b0, b1);
            }
            float ma = maskadd[nb * 8 + 2 * tig];
            float mb = maskadd[nb * 8 + 2 * tig + 1];
            sc[nb][0] += ma; sc[nb][1] += mb;
            sc[nb][2] += ma; sc[nb][3] += mb;
        }

        // --- row max (rows r0=grp, r1=grp+8 of this warp's 16) ---
        float rm0 = -1e30f, rm1 = -1e30f;
        #pragma unroll
        for (int nb = 0; nb < 8; nb++) {
            rm0 = fmaxf(rm0, fmaxf(sc[nb][0], sc[nb][1]));
            rm1 = fmaxf(rm1, fmaxf(sc[nb][2], sc[nb][3]));
        }
        rm0 = fmaxf(rm0, __shfl_xor_sync(0xffffffffu, rm0, 1));
        rm0 = fmaxf(rm0, __shfl_xor_sync(0xffffffffu, rm0, 2));
        rm1 = fmaxf(rm1, __shfl_xor_sync(0xffffffffu, rm1, 1));
        rm1 = fmaxf(rm1, __shfl_xor_sync(0xffffffffu, rm1, 2));

        float mn0 = fmaxf(m0, rm0);
        float mn1 = fmaxf(m1, rm1);
        float corr0 = __expf(m0 - mn0);
        float corr1 = __expf(m1 - mn1);
        m0 = mn0; m1 = mn1;
        l0 *= corr0; l1 *= corr1;
        #pragma unroll
        for (int nb = 0; nb < 4; nb++) {
            o[nb][0] *= corr0; o[nb][1] *= corr0;
            o[nb][2] *= corr1; o[nb][3] *= corr1;
        }

        // --- P = exp(S - m); store tf32 P to smem (per-warp private band) ---
        const int pr0 = warp * 16 + grp;
        #pragma unroll
        for (int nb = 0; nb < 8; nb++) {
            float p0 = __expf(sc[nb][0] - mn0);
            float p1 = __expf(sc[nb][1] - mn0);
            float p2 = __expf(sc[nb][2] - mn1);
            float p3 = __expf(sc[nb][3] - mn1);
            l0 += p0 + p1;
            l1 += p2 + p3;
            int col = nb * 8 + 2 * tig;
            Ps[pr0][col]     = f2tf(p0);
            Ps[pr0][col + 1] = f2tf(p1);
            Ps[pr0 + 8][col]     = f2tf(p2);
            Ps[pr0 + 8][col + 1] = f2tf(p3);
        }
        __syncwarp();

        // --- O += P V  (A = P from smem, B = V^T from smem) ---
        #pragma unroll
        for (int kc = 0; kc < 8; kc++) {
            uint32_t pa[4];
            pa[0] = Ps[warp * 16 + grp][kc * 8 + tig];
            pa[1] = Ps[warp * 16 + grp + 8][kc * 8 + tig];
            pa[2] = Ps[warp * 16 + grp][kc * 8 + tig + 4];
            pa[3] = Ps[warp * 16 + grp + 8][kc * 8 + tig + 4];
            #pragma unroll
            for (int nb = 0; nb < 4; nb++) {
                uint32_t b0 = Vt[nb * 8 + grp][kc * 8 + tig];
                uint32_t b1 = Vt[nb * 8 + grp][kc * 8 + tig + 4];
                mma_tf32(o[nb], pa, b0, b1);
            }
        }
        __syncwarp();
    }

    // --- epilogue: row-sum reduce over quad, normalize, write ---
    l0 += __shfl_xor_sync(0xffffffffu, l0, 1);
    l0 += __shfl_xor_sync(0xffffffffu, l0, 2);
    l1 += __shfl_xor_sync(0xffffffffu, l1, 1);
    l1 += __shfl_xor_sync(0xffffffffu, l1, 2);
    float inv0 = (l0 > 0.0f) ? (1.0f / l0) : 0.0f;
    float inv1 = (l1 > 0.0f) ? (1.0f / l1) : 0.0f;

    #pragma unroll
    for (int nb = 0; nb < 4; nb++) {
        int col = head * HD + nb * 8 + 2 * tig;
        float2 w0 = make_float2(o[nb][0] * inv0, o[nb][1] * inv0);
        float2 w1 = make_float2(o[nb][2] * inv1, o[nb][3] * inv1);
        *(float2*)&g_ao[qr0 * CDIM + col] = w0;
        *(float2*)&g_ao[qr1 * CDIM + col] = w1;
    }
}

// ============================================================
extern "C" void kernel_launch(void* const* d_in, const int* in_sizes, int n_in,
                              void* d_out, int out_size) {
    const float* x      = (const float*)d_in[0];
    const float* dbz    = (const float*)d_in[1];
    const float* qkv_w  = (const float*)d_in[2];
    const float* proj_w = (const float*)d_in[3];
    const float* proj_b = (const float*)d_in[4];
    float* out = (float*)d_out;

    keep_kernel<<<16, 256>>>(dbz);
    gemm_kernel<0><<<dim3(768 / BN, N_TOK / BM), 256>>>(x, qkv_w, nullptr, nullptr, nullptr);
    flash_tc_kernel<<<dim3(N_TOK / 64, NH), 128>>>();
    gemm_kernel<1><<<dim3(CDIM / BN, N_TOK / BM), 256>>>(nullptr, proj_w, proj_b, x, out);
}

// round 4
// speedup vs baseline: 3.5881x; 1.3796x over previous
#include <cuda_runtime.h>
#include <math.h>
#include <stdint.h>

#define N_TOK 4096
#define CDIM 256
#define NH 8
#define HD 32
#define SCALE_F 0.17677669529663687f           // 32^-0.5
#define QSCALE (0.17677669529663687f * 1.4426950408889634f)  // scale * log2(e)

// ---- scratch (device globals) ----
__device__ float g_q[NH * N_TOK * HD];
__device__ float g_k[NH * N_TOK * HD];
__device__ float g_v[NH * N_TOK * HD];
__device__ float g_ao[N_TOK * CDIM];
__device__ float g_kmask[N_TOK];          // 0.f kept, -1e30f dropped

// ============================================================
__device__ __forceinline__ uint32_t f2tf(float f) {
    uint32_t r; asm("cvt.rna.tf32.f32 %0, %1;" : "=r"(r) : "f"(f)); return r;
}
__device__ __forceinline__ float ex2(float x) {
    float r; asm("ex2.approx.ftz.f32 %0, %1;" : "=f"(r) : "f"(x)); return r;
}
__device__ __forceinline__ void mma_tf32(float c[4], const uint32_t a[4],
                                         uint32_t b0, uint32_t b1) {
    asm volatile(
        "mma.sync.aligned.m16n8k8.row.col.f32.tf32.tf32.f32 "
        "{%0,%1,%2,%3},{%4,%5,%6,%7},{%8,%9},{%0,%1,%2,%3};"
        : "+f"(c[0]), "+f"(c[1]), "+f"(c[2]), "+f"(c[3])
        : "r"(a[0]), "r"(a[1]), "r"(a[2]), "r"(a[3]), "r"(b0), "r"(b1));
}

// ============================================================
// Keep mask: keep = 3x3 dilation of (dbz >= 15)
// ============================================================
__global__ void keep_kernel(const float* __restrict__ dbz) {
    int n = blockIdx.x * 256 + threadIdx.x;
    if (n >= N_TOK) return;
    int t   = n >> 10;
    int rem = n & 1023;
    int y   = rem >> 5;
    int x   = rem & 31;
    const float* d = dbz + t * 1024;
    bool k = false;
    #pragma unroll
    for (int dy = -1; dy <= 1; dy++) {
        int yy = y + dy;
        if (yy < 0 || yy >= 32) continue;
        #pragma unroll
        for (int dx = -1; dx <= 1; dx++) {
            int xx = x + dx;
            if (xx < 0 || xx >= 32) continue;
            k = k || (d[yy * 32 + xx] >= 15.0f);
        }
    }
    g_kmask[n] = k ? 0.0f : -1e30f;
}

// ============================================================
// Tensor-core tf32 GEMM: C[M,N] = A[M,256] * B[N,256]^T
// CTA tile 128x64, BK=32, 8 warps (4x2), warp tile 32x32.
// MODE 0: qkv -> scatter head-major q/k/v. MODE 1: proj epilogue.
// ============================================================
template <int MODE>
__global__ __launch_bounds__(256) void gemm_tc(
    const float* __restrict__ A, const float* __restrict__ B,
    const float* __restrict__ bias, const float* __restrict__ xres,
    float* __restrict__ out)
{
    __shared__ __align__(16) uint32_t As[128][36];
    __shared__ __align__(16) uint32_t Bs[64][36];

    const float* Ap = (MODE == 0) ? A : g_ao;

    const int tid  = threadIdx.x;
    const int warp = tid >> 5;
    const int lane = tid & 31;
    const int grp  = lane >> 2;
    const int tig  = lane & 3;
    const int wm   = warp >> 1;       // 0..3
    const int wn   = warp & 1;        // 0..1
    const int row0 = blockIdx.y * 128;
    const int col0 = blockIdx.x * 64;

    float acc[2][4][4];
    #pragma unroll
    for (int mi = 0; mi < 2; mi++)
        #pragma unroll
        for (int ni = 0; ni < 4; ni++)
            #pragma unroll
            for (int j = 0; j < 4; j++) acc[mi][ni][j] = 0.0f;

    for (int k0 = 0; k0 < CDIM; k0 += 32) {
        __syncthreads();
        // stage A tile (128x32) in fragment order: c' = j*8 + (kq>>1)*2 + (kq&1)
        #pragma unroll
        for (int t = 0; t < 4; t++) {
            int idx = tid + t * 256;
            int r = idx >> 3, kq = idx & 7;
            float4 v = *(const float4*)&Ap[(row0 + r) * CDIM + k0 + kq * 4];
            int cb = ((kq >> 1) << 1) | (kq & 1);
            As[r][cb]      = f2tf(v.x);
            As[r][cb + 8]  = f2tf(v.y);
            As[r][cb + 16] = f2tf(v.z);
            As[r][cb + 24] = f2tf(v.w);
        }
        // stage B tile (64x32)
        #pragma unroll
        for (int t = 0; t < 2; t++) {
            int idx = tid + t * 256;
            int r = idx >> 3, kq = idx & 7;
            float4 v = *(const float4*)&B[(col0 + r) * CDIM + k0 + kq * 4];
            int cb = ((kq >> 1) << 1) | (kq & 1);
            Bs[r][cb]      = f2tf(v.x);
            Bs[r][cb + 8]  = f2tf(v.y);
            Bs[r][cb + 16] = f2tf(v.z);
            Bs[r][cb + 24] = f2tf(v.w);
        }
        __syncthreads();

        uint32_t alo[2][8], ahi[2][8], bb[4][8];
        #pragma unroll
        for (int mi = 0; mi < 2; mi++) {
            int r = wm * 32 + mi * 16 + grp;
            *(uint4*)&alo[mi][0] = *(const uint4*)&As[r][tig * 8];
            *(uint4*)&alo[mi][4] = *(const uint4*)&As[r][tig * 8 + 4];
            *(uint4*)&ahi[mi][0] = *(const uint4*)&As[r + 8][tig * 8];
            *(uint4*)&ahi[mi][4] = *(const uint4*)&As[r + 8][tig * 8 + 4];
        }
        #pragma unroll
        for (int ni = 0; ni < 4; ni++) {
            int c = wn * 32 + ni * 8 + grp;
            *(uint4*)&bb[ni][0] = *(const uint4*)&Bs[c][tig * 8];
            *(uint4*)&bb[ni][4] = *(const uint4*)&Bs[c][tig * 8 + 4];
        }
        #pragma unroll
        for (int kc = 0; kc < 4; kc++)
            #pragma unroll
            for (int mi = 0; mi < 2; mi++) {
                uint32_t a[4] = {alo[mi][kc * 2], ahi[mi][kc * 2],
                                 alo[mi][kc * 2 + 1], ahi[mi][kc * 2 + 1]};
                #pragma unroll
                for (int ni = 0; ni < 4; ni++)
                    mma_tf32(acc[mi][ni], a, bb[ni][kc * 2], bb[ni][kc * 2 + 1]);
            }
    }

    // epilogue
    #pragma unroll
    for (int mi = 0; mi < 2; mi++) {
        int rA = row0 + wm * 32 + mi * 16 + grp;
        #pragma unroll
        for (int half = 0; half < 2; half++) {
            int n = rA + half * 8;
            #pragma unroll
            for (int ni = 0; ni < 4; ni++) {
                int c = col0 + wn * 32 + ni * 8 + 2 * tig;
                float v0 = acc[mi][ni][half * 2 + 0];
                float v1 = acc[mi][ni][half * 2 + 1];
                if (MODE == 0) {
                    int part = c >> 8;
                    int cc   = c & 255;
                    int hh   = cc >> 5;
                    int dd   = cc & 31;
                    float* dst = (part == 0) ? g_q : (part == 1) ? g_k : g_v;
                    *(float2*)&dst[(hh * N_TOK + n) * HD + dd] = make_float2(v0, v1);
                } else {
                    bool keep = (g_kmask[n] == 0.0f);
                    float2 bv = *(const float2*)&bias[c];
                    float2 xr = *(const float2*)&xres[n * CDIM + c];
                    float o0 = (keep ? (v0 + bv.x) : 0.0f) + xr.x;
                    float o1 = (keep ? (v1 + bv.y) : 0.0f) + xr.y;
                    *(float2*)&out[n * CDIM + c] = make_float2(o0, o1);
                }
            }
        }
    }
}

// ============================================================
// Flash attention (tf32 tensor cores), 128 queries/CTA, 8 warps.
// K tile 64. Fragment-order smem; P kept in registers (shuffle C->A).
// Softmax in exp2 domain (log2e folded into Q scale).
// ============================================================
__global__ __launch_bounds__(256) void flash_tc_kernel() {
    const int head = blockIdx.y;
    const int qt   = blockIdx.x * 128;
    const int tid  = threadIdx.x;
    const int warp = tid >> 5;
    const int lane = tid & 31;
    const int grp  = lane >> 2;
    const int tig  = lane & 3;

    const float* Q = g_q + head * N_TOK * HD;
    const float* K = g_k + head * N_TOK * HD;
    const float* V = g_v + head * N_TOK * HD;

    __shared__ __align__(16) uint32_t Ksf[64][36];     // [key][fragment-order d]
    __shared__ __align__(16) uint32_t Vtf[2][32][34];  // [key-half][d][frag-order key]
    __shared__ float maskadd[64];

    // --- Q A-fragments (one-time), pre-scaled by scale*log2e ---
    const int qr0 = qt + warp * 16 + grp;
    const int qr1 = qr0 + 8;
    uint32_t qa[4][4];
    #pragma unroll
    for (int kc = 0; kc < 4; kc++) {
        int c0 = kc * 8 + tig;
        qa[kc][0] = f2tf(Q[qr0 * HD + c0]     * QSCALE);
        qa[kc][1] = f2tf(Q[qr1 * HD + c0]     * QSCALE);
        qa[kc][2] = f2tf(Q[qr0 * HD + c0 + 4] * QSCALE);
        qa[kc][3] = f2tf(Q[qr1 * HD + c0 + 4] * QSCALE);
    }

    float m0 = -1e30f, m1 = -1e30f, l0 = 0.0f, l1 = 0.0f;
    float o[4][4];
    #pragma unroll
    for (int nb = 0; nb < 4; nb++)
        #pragma unroll
        for (int j = 0; j < 4; j++) o[nb][j] = 0.0f;

    const int srcA = (lane & 28) | (tig >> 1);
    const int srcB = srcA + 2;
    const bool oddt = (tig & 1);

    for (int kt = 0; kt < N_TOK; kt += 64) {
        __syncthreads();
        // --- stage K and V tiles (512 float4 each, 2 per thread each) ---
        #pragma unroll
        for (int t = 0; t < 2; t++) {
            int idx = tid + t * 256;         // 0..511
            int key = idx >> 3, dq = idx & 7;
            float4 kv = *(const float4*)&K[(kt + key) * HD + dq * 4];
            int cb = ((dq >> 1) << 1) | (dq & 1);
            Ksf[key][cb]      = f2tf(kv.x);
            Ksf[key][cb + 8]  = f2tf(kv.y);
            Ksf[key][cb + 16] = f2tf(kv.z);
            Ksf[key][cb + 24] = f2tf(kv.w);
            float4 vv = *(const float4*)&V[(kt + key) * HD + dq * 4];
            int half = key >> 5;
            int vc = ((key & 3) << 3) | (((key >> 3) & 3) << 1) | ((key >> 2) & 1);
            int d0 = dq * 4;
            Vtf[half][d0 + 0][vc] = f2tf(vv.x);
            Vtf[half][d0 + 1][vc] = f2tf(vv.y);
            Vtf[half][d0 + 2][vc] = f2tf(vv.z);
            Vtf[half][d0 + 3][vc] = f2tf(vv.w);
        }
        if (tid < 64) maskadd[tid] = g_kmask[kt + tid];
        __syncthreads();

        // --- S = Q K^T (scores in log2 domain) ---
        float sc[8][4];
        #pragma unroll
        for (int nb = 0; nb < 8; nb++) {
            uint32_t kb[8];
            *(uint4*)&kb[0] = *(const uint4*)&Ksf[nb * 8 + grp][tig * 8];
            *(uint4*)&kb[4] = *(const uint4*)&Ksf[nb * 8 + grp][tig * 8 + 4];
            sc[nb][0] = sc[nb][1] = sc[nb][2] = sc[nb][3] = 0.0f;
            #pragma unroll
            for (int kc = 0; kc < 4; kc++)
                mma_tf32(sc[nb], qa[kc], kb[kc * 2], kb[kc * 2 + 1]);
            float ma = maskadd[nb * 8 + 2 * tig];
            float mb = maskadd[nb * 8 + 2 * tig + 1];
            sc[nb][0] += ma; sc[nb][1] += mb;
            sc[nb][2] += ma; sc[nb][3] += mb;
        }

        // --- online softmax bookkeeping ---
        float rm0 = -1e30f, rm1 = -1e30f;
        #pragma unroll
        for (int nb = 0; nb < 8; nb++) {
            rm0 = fmaxf(rm0, fmaxf(sc[nb][0], sc[nb][1]));
            rm1 = fmaxf(rm1, fmaxf(sc[nb][2], sc[nb][3]));
        }
        rm0 = fmaxf(rm0, __shfl_xor_sync(0xffffffffu, rm0, 1));
        rm0 = fmaxf(rm0, __shfl_xor_sync(0xffffffffu, rm0, 2));
        rm1 = fmaxf(rm1, __shfl_xor_sync(0xffffffffu, rm1, 1));
        rm1 = fmaxf(rm1, __shfl_xor_sync(0xffffffffu, rm1, 2));

        float mn0 = fmaxf(m0, rm0);
        float mn1 = fmaxf(m1, rm1);
        float corr0 = ex2(m0 - mn0);
        float corr1 = ex2(m1 - mn1);
        m0 = mn0; m1 = mn1;
        l0 *= corr0; l1 *= corr1;
        #pragma unroll
        for (int nb = 0; nb < 4; nb++) {
            o[nb][0] *= corr0; o[nb][1] *= corr0;
            o[nb][2] *= corr1; o[nb][3] *= corr1;
        }

        // --- P = 2^(S-m), convert to tf32 in registers ---
        uint32_t up[8][4];
        #pragma unroll
        for (int nb = 0; nb < 8; nb++) {
            float p0 = ex2(sc[nb][0] - mn0);
            float p1 = ex2(sc[nb][1] - mn0);
            float p2 = ex2(sc[nb][2] - mn1);
            float p3 = ex2(sc[nb][3] - mn1);
            l0 += p0 + p1;
            l1 += p2 + p3;
            up[nb][0] = f2tf(p0); up[nb][1] = f2tf(p1);
            up[nb][2] = f2tf(p2); up[nb][3] = f2tf(p3);
        }

        // --- O += P V : C-frag -> A-frag via shuffles, V b-frags via LDS.64 ---
        #pragma unroll
        for (int kc = 0; kc < 8; kc++) {
            uint32_t s0 = __shfl_sync(0xffffffffu, up[kc][0], srcA);
            uint32_t s1 = __shfl_sync(0xffffffffu, up[kc][1], srcA);
            uint32_t s2 = __shfl_sync(0xffffffffu, up[kc][2], srcA);
            uint32_t s3 = __shfl_sync(0xffffffffu, up[kc][3], srcA);
            uint32_t t0 = __shfl_sync(0xffffffffu, up[kc][0], srcB);
            uint32_t t1 = __shfl_sync(0xffffffffu, up[kc][1], srcB);
            uint32_t t2 = __shfl_sync(0xffffffffu, up[kc][2], srcB);
            uint32_t t3 = __shfl_sync(0xffffffffu, up[kc][3], srcB);
            uint32_t pa[4];
            pa[0] = oddt ? s1 : s0;
            pa[1] = oddt ? s3 : s2;
            pa[2] = oddt ? t1 : t0;
            pa[3] = oddt ? t3 : t2;
            int hf = kc >> 2;
            int co = tig * 8 + ((kc & 3) << 1);
            #pragma unroll
            for (int nb = 0; nb < 4; nb++) {
                uint2 bv = *(const uint2*)&Vtf[hf][nb * 8 + grp][co];
                mma_tf32(o[nb], pa, bv.x, bv.y);
            }
        }
    }

    // --- epilogue ---
    l0 += __shfl_xor_sync(0xffffffffu, l0, 1);
    l0 += __shfl_xor_sync(0xffffffffu, l0, 2);
    l1 += __shfl_xor_sync(0xffffffffu, l1, 1);
    l1 += __shfl_xor_sync(0xffffffffu, l1, 2);
    float inv0 = (l0 > 0.0f) ? (1.0f / l0) : 0.0f;
    float inv1 = (l1 > 0.0f) ? (1.0f / l1) : 0.0f;

    #pragma unroll
    for (int nb = 0; nb < 4; nb++) {
        int col = head * HD + nb * 8 + 2 * tig;
        *(float2*)&g_ao[qr0 * CDIM + col] = make_float2(o[nb][0] * inv0, o[nb][1] * inv0);
        *(float2*)&g_ao[qr1 * CDIM + col] = make_float2(o[nb][2] * inv1, o[nb][3] * inv1);
    }
}

// ============================================================
extern "C" void kernel_launch(void* const* d_in, const int* in_sizes, int n_in,
                              void* d_out, int out_size) {
    const float* x      = (const float*)d_in[0];
    const float* dbz    = (const float*)d_in[1];
    const float* qkv_w  = (const float*)d_in[2];
    const float* proj_w = (const float*)d_in[3];
    const float* proj_b = (const float*)d_in[4];
    float* out = (float*)d_out;

    keep_kernel<<<16, 256>>>(dbz);
    gemm_tc<0><<<dim3(768 / 64, N_TOK / 128), 256>>>(x, qkv_w, nullptr, nullptr, nullptr);
    flash_tc_kernel<<<dim3(N_TOK / 128, NH), 256>>>();
    gemm_tc<1><<<dim3(CDIM / 64, N_TOK / 128), 256>>>(nullptr, proj_w, proj_b, x, out);
}